// round 1
// baseline (speedup 1.0000x reference)
#include <cuda_runtime.h>
#include <cuda_bf16.h>
#include <cstdint>

// ---------------------------------------------------------------------------
// HungarianMatcher cost matrix:
//   C[b,q,t] = 2*focal(pl[b,q,cls[t]]) + 5*L1(pb[b,q], tb[t]) - 2*giou(...)
// Shapes: B=16 Q=900 C=91 T=4800  -> out [14400, 4800] fp32 (276 MB)
//
// Strategy:
//  prep kernels (tiny): focal table F2[row][c] = 2*(pos-neg)  (all exp/log here)
//                       row boxes: cxcywh*5, xyxy, area
//                       tgt boxes: cxcywh*5, xyxy, area, cls
//  main kernel: tiled 16 rows x 256 targets per block, F table staged in smem,
//               1 rcp.approx per element (merged giou denominator),
//               vectorized streaming stores.
// ---------------------------------------------------------------------------

#define BQ_MAX   14400
#define T_MAX    4800
#define CP       92            // padded class stride (91 -> 92)

__device__ float  g_F[BQ_MAX * CP];       // 2*(pos-neg) focal cost, prescaled
__device__ float4 g_rowA[BQ_MAX];          // cxcywh * 5
__device__ float4 g_rowB[BQ_MAX];          // xyxy
__device__ float  g_rowArea[BQ_MAX];
__device__ float4 g_tgtA[T_MAX];           // cxcywh * 5
__device__ float4 g_tgtB[T_MAX];           // xyxy
__device__ float  g_tgtArea[T_MAX];
__device__ int    g_tgtCls[T_MAX];

__device__ __forceinline__ float frcp_approx(float x) {
    float r;
    asm("rcp.approx.f32 %0, %1;" : "=f"(r) : "f"(x));
    return r;
}

// ---------------------------- prep: focal table ----------------------------
__global__ void prep_focal(const float* __restrict__ logits, int BQ, int C) {
    int i = blockIdx.x * blockDim.x + threadIdx.x;
    if (i >= BQ * C) return;
    int row = i / C;
    int c   = i - row * C;
    float x = logits[i];
    float e = __expf(-x);
    float inv = frcp_approx(1.0f + e);
    float p = inv;          // sigmoid(x)
    float q = e * inv;      // 1 - sigmoid(x), computed without cancellation
    // F2 = 2*( 0.25*q^2*(-log(p+eps)) - 0.75*p^2*(-log(q+eps)) )
    float lp = __logf(p + 1e-8f);
    float lq = __logf(q + 1e-8f);
    float F2 = -0.5f * q * q * lp + 1.5f * p * p * lq;
    g_F[row * CP + c] = F2;
}

// ---------------------------- prep: row boxes -------------------------------
__global__ void prep_rows(const float* __restrict__ boxes, int BQ) {
    int r = blockIdx.x * blockDim.x + threadIdx.x;
    if (r >= BQ) return;
    float4 b = reinterpret_cast<const float4*>(boxes)[r];  // cx,cy,w,h
    g_rowA[r] = make_float4(5.f*b.x, 5.f*b.y, 5.f*b.z, 5.f*b.w);
    float x0 = b.x - 0.5f*b.z, y0 = b.y - 0.5f*b.w;
    float x1 = b.x + 0.5f*b.z, y1 = b.y + 0.5f*b.w;
    g_rowB[r] = make_float4(x0, y0, x1, y1);
    g_rowArea[r] = (x1 - x0) * (y1 - y0);
}

// ---------------------------- prep: tgt boxes -------------------------------
__global__ void prep_tgts(const float* __restrict__ boxes,
                          const int* __restrict__ ids, int T) {
    int t = blockIdx.x * blockDim.x + threadIdx.x;
    if (t >= T) return;
    float4 b = reinterpret_cast<const float4*>(boxes)[t];
    g_tgtA[t] = make_float4(5.f*b.x, 5.f*b.y, 5.f*b.z, 5.f*b.w);
    float x0 = b.x - 0.5f*b.z, y0 = b.y - 0.5f*b.w;
    float x1 = b.x + 0.5f*b.z, y1 = b.y + 0.5f*b.w;
    g_tgtB[t] = make_float4(x0, y0, x1, y1);
    g_tgtArea[t] = (x1 - x0) * (y1 - y0);
    g_tgtCls[t] = ids[t] - 1;
}

// ---------------------------- main kernel -----------------------------------
// Block: 256 threads, tile = 16 rows x 256 targets.
// Thread: rr = tid>>6 (4 row-groups), tt = tid&63 -> 4 contiguous targets.
// Each thread computes 4 rows x 4 targets, stores float4 per row.
#define ROW_TILE 16
#define TGT_TILE 256

__global__ __launch_bounds__(256) void cost_kernel(float* __restrict__ out,
                                                   int BQ, int T) {
    __shared__ float  sF[ROW_TILE * CP];
    __shared__ float4 sRowA[ROW_TILE];
    __shared__ float4 sRowB[ROW_TILE];
    __shared__ float  sRowArea[ROW_TILE];

    const int tid  = threadIdx.x;
    const int row0 = blockIdx.y * ROW_TILE;

    // stage focal table rows (layout matches global: CP stride)
    #pragma unroll
    for (int i = tid; i < ROW_TILE * CP; i += 256)
        sF[i] = g_F[row0 * CP + i];
    if (tid < ROW_TILE) {
        sRowA[tid]    = g_rowA[row0 + tid];
        sRowB[tid]    = g_rowB[row0 + tid];
        sRowArea[tid] = g_rowArea[row0 + tid];
    }
    __syncthreads();

    const int tt = tid & 63;
    const int rr = tid >> 6;
    const int j0 = blockIdx.x * TGT_TILE + tt * 4;
    if (j0 >= T) return;

    // 4 targets in registers
    float4 ta[4], tb[4];
    float  tar[4];
    int    tcl[4];
    #pragma unroll
    for (int k = 0; k < 4; ++k) {
        ta[k]  = g_tgtA[j0 + k];
        tb[k]  = g_tgtB[j0 + k];
        tar[k] = g_tgtArea[j0 + k];
        tcl[k] = g_tgtCls[j0 + k];
    }

    #pragma unroll
    for (int r = 0; r < 4; ++r) {
        const int rowL = (rr << 2) + r;
        const float4 rcA = sRowA[rowL];
        const float4 rbB = sRowB[rowL];
        const float  rar = sRowArea[rowL];
        const int    frow = rowL * CP;

        float4 res;
        float* resp = &res.x;
        #pragma unroll
        for (int k = 0; k < 4; ++k) {
            float f2 = sF[frow + tcl[k]];

            // 5 * L1 (coords prescaled by 5)
            float bx = fabsf(rcA.x - ta[k].x) + fabsf(rcA.y - ta[k].y)
                     + fabsf(rcA.z - ta[k].z) + fabsf(rcA.w - ta[k].w);

            // giou (merged single-reciprocal form)
            float ltx = fmaxf(rbB.x, tb[k].x);
            float lty = fmaxf(rbB.y, tb[k].y);
            float rbx = fminf(rbB.z, tb[k].z);
            float rby = fminf(rbB.w, tb[k].w);
            float iw  = fmaxf(rbx - ltx, 0.0f);
            float ih  = fmaxf(rby - lty, 0.0f);
            float inter = iw * ih;
            float uni   = rar + tar[k] - inter;

            float ex0 = fminf(rbB.x, tb[k].x);
            float ey0 = fminf(rbB.y, tb[k].y);
            float ex1 = fmaxf(rbB.z, tb[k].z);
            float ey1 = fmaxf(rbB.w, tb[k].w);
            float enc = (ex1 - ex0) * (ey1 - ey0);

            float u = fmaxf(uni, 1e-6f);
            float e = fmaxf(enc, 1e-6f);
            // giou = inter/u - (enc-uni)/e = num / (u*e)
            float num = inter * e - (enc - uni) * u;
            float inv = frcp_approx(u * e);

            // out = f2 + bx - 2*giou
            resp[k] = fmaf(num * inv, -2.0f, f2 + bx);
        }

        // streaming vector store (write-once 276MB output; keep L2 for F)
        float* dst = out + (size_t)(row0 + rowL) * T + j0;
        asm volatile("st.global.cs.v4.f32 [%0], {%1,%2,%3,%4};"
                     :: "l"(dst), "f"(res.x), "f"(res.y), "f"(res.z), "f"(res.w));
    }
}

// ---------------------------------------------------------------------------
extern "C" void kernel_launch(void* const* d_in, const int* in_sizes, int n_in,
                              void* d_out, int out_size) {
    const float* pred_logits = (const float*)d_in[0];
    const float* pred_boxes  = (const float*)d_in[1];
    const int*   tgt_ids     = (const int*)d_in[2];
    const float* tgt_boxes   = (const float*)d_in[3];
    float* out = (float*)d_out;

    const int BQ = in_sizes[1] / 4;          // 14400
    const int C  = in_sizes[0] / BQ;         // 91
    const int T  = in_sizes[2];              // 4800

    prep_focal<<<(BQ * C + 255) / 256, 256>>>(pred_logits, BQ, C);
    prep_rows <<<(BQ + 255) / 256, 256>>>(pred_boxes, BQ);
    prep_tgts <<<(T + 255) / 256, 256>>>(tgt_boxes, tgt_ids, T);

    dim3 grid((T + TGT_TILE - 1) / TGT_TILE, (BQ + ROW_TILE - 1) / ROW_TILE);
    cost_kernel<<<grid, 256>>>(out, BQ, T);
}